// round 14
// baseline (speedup 1.0000x reference)
#include <cuda_runtime.h>
#include <math.h>
#include <stdint.h>

// ---------------- problem constants ----------------
#define BB    16
#define TT    32
#define CC    3
#define HH    64
#define WW    64
#define DD    512
#define LL    6
#define BT    512          // B*T
#define NTOK  64           // tokens per frame (8x8)
#define M_CONV 32768       // B*T*NTOK
#define K_CONV 576         // C*KT*P*P
#define EPSV  1e-5f

#define SA    20           // As row stride (floats)
#define SB    72           // Bs row stride (floats)
#define SB2   200          // fused-kernel Bs row stride (192 cols + pad)
#define SKV   193          // fused attn kqv row stride (conflict-free)

#define NBLK  128          // persistent megakernel grid

// ---------------- scratch (device globals; no allocation) ----------------
__device__ float g_tok[M_CONV * DD];
__device__ float g_wT [K_CONV * DD];     // transposed conv weight, tf32-pre-rounded
__device__ float g_h  [BT * DD];
__device__ float g_xi [BT * DD];         // LN output, tf32-pre-rounded
__device__ float g_yv [BT * DD];         // attn output, tf32-pre-rounded
__device__ float g_mid[BT * 4 * DD];     // gelu output, tf32-pre-rounded
__device__ float g_ropes[TT * 32];
__device__ float g_ropec[TT * 32];

// ---------------- grid barrier state ----------------
__device__ unsigned g_bar = 0;
__device__ unsigned g_gen = 0;

// ---------------- helpers ----------------
__device__ __forceinline__ uint32_t f2tf(float f) {
    uint32_t u;
    asm("cvt.rna.tf32.f32 %0, %1;" : "=r"(u) : "f"(f));
    return u;
}
__device__ __forceinline__ float f2tf_f(float f) {
    return __uint_as_float(f2tf(f));
}

__device__ __forceinline__ void mma1688(float* c, const uint32_t* a, const uint32_t* b) {
    asm volatile(
        "mma.sync.aligned.m16n8k8.row.col.f32.tf32.tf32.f32 "
        "{%0,%1,%2,%3}, {%4,%5,%6,%7}, {%8,%9}, {%0,%1,%2,%3};"
        : "+f"(c[0]), "+f"(c[1]), "+f"(c[2]), "+f"(c[3])
        : "r"(a[0]), "r"(a[1]), "r"(a[2]), "r"(a[3]), "r"(b[0]), "r"(b[1]));
}

__device__ __forceinline__ void cp16(void* smem, const void* gmem) {
    uint32_t s = (uint32_t)__cvta_generic_to_shared(smem);
    asm volatile("cp.async.cg.shared.global [%0], [%1], 16;\n" :: "r"(s), "l"(gmem));
}
__device__ __forceinline__ void cp16z(void* smem, const void* gmem, bool pred) {
    uint32_t s = (uint32_t)__cvta_generic_to_shared(smem);
    int sz = pred ? 16 : 0;
    asm volatile("cp.async.cg.shared.global [%0], [%1], 16, %2;\n" :: "r"(s), "l"(gmem), "r"(sz));
}
__device__ __forceinline__ void cp_commit() {
    asm volatile("cp.async.commit_group;\n");
}
template<int N>
__device__ __forceinline__ void cp_wait() {
    asm volatile("cp.async.wait_group %0;\n" :: "n"(N));
}

// sense-reversing grid barrier: safe because all NBLK blocks are co-resident
__device__ __forceinline__ void grid_sync() {
    __syncthreads();
    if (threadIdx.x == 0) {
        unsigned gen = *(volatile unsigned*)&g_gen;
        __threadfence();
        if (atomicAdd(&g_bar, 1u) == NBLK - 1) {
            g_bar = 0;
            __threadfence();
            atomicAdd(&g_gen, 1u);
        } else {
            while (*(volatile unsigned*)&g_gen == gen) { }
        }
        __threadfence();
    }
    __syncthreads();
}

// ---------------- weight transpose (+ tf32 pre-round) ----------------
__global__ void transpose_w_kernel(const float* __restrict__ w) {
    int idx = blockIdx.x * 256 + threadIdx.x;
    if (idx < DD * K_CONV) {
        int d = idx / K_CONV, k = idx - d * K_CONV;
        g_wT[k * DD + d] = f2tf_f(w[idx]);
    }
}

// ---------------- RoPE table ----------------
__global__ void rope_kernel() {
    int tid = threadIdx.x;          // 1024 threads
    int t = tid >> 5, d0 = tid & 31;
    float freq = exp2f(-(float)d0 * (13.287712379549449f / 32.f));
    float ang = (float)t * freq;
    float s, c;
    sincosf(ang, &s, &c);
    g_ropes[tid] = s;
    g_ropec[tid] = c;
}

// ---- conv warp tile 32x32 (2 m16 x 4 n8): A needs cvt, B pre-rounded ----
__device__ __forceinline__ void mma_tile_conv(
    const float* As, const float* Bs, int warp_m, int warp_n, int lane, float c[2][4][4])
{
    int g  = lane >> 2;
    int tg = lane & 3;
    const uint32_t* Bu = (const uint32_t*)Bs;
    #pragma unroll
    for (int ks = 0; ks < 16; ks += 8) {
        uint32_t a[2][4], b[4][2];
        #pragma unroll
        for (int mt = 0; mt < 2; mt++) {
            int r0 = warp_m + mt * 16 + g;
            a[mt][0] = f2tf(As[(r0    ) * SA + ks + tg    ]);
            a[mt][1] = f2tf(As[(r0 + 8) * SA + ks + tg    ]);
            a[mt][2] = f2tf(As[(r0    ) * SA + ks + tg + 4]);
            a[mt][3] = f2tf(As[(r0 + 8) * SA + ks + tg + 4]);
        }
        #pragma unroll
        for (int nt = 0; nt < 4; nt++) {
            int col = warp_n + nt * 8 + g;
            b[nt][0] = Bu[(ks + tg    ) * SB + col];
            b[nt][1] = Bu[(ks + tg + 4) * SB + col];
        }
        #pragma unroll
        for (int mt = 0; mt < 2; mt++)
            #pragma unroll
            for (int nt = 0; nt < 4; nt++)
                mma1688(c[mt][nt], a[mt], b[nt]);
    }
}

// ---------------- conv as GEMM (im2col, tf32 TC, 3-stage cp.async) --------
__global__ __launch_bounds__(256) void conv_gemm_tc(
    const float* __restrict__ x, const float* __restrict__ bias)
{
    constexpr int BM = 128;
    constexpr int ST = 3;
    __shared__ float As[ST][BM * SA];
    __shared__ float Bs[ST][16 * SB];
    int tid = threadIdx.x;
    int warp = tid >> 5, lane = tid & 31;
    int m0 = blockIdx.y * BM, n0 = blockIdx.x * 64;

    int kk = (tid & 3) << 2;
    const float* xb[2];
    int trow[2], arow[2];
    #pragma unroll
    for (int p = 0; p < 2; p++) {
        int row = p * 64 + (tid >> 2);
        arow[p] = row;
        int m = m0 + row;
        int b = m >> 11;
        int t = (m >> 6) & 31;
        int n = m & 63;
        int hn = n >> 3, wn = n & 7;
        xb[p]  = x + b * (TT * CC * HH * WW) + (hn * 8) * WW + wn * 8;
        trow[p] = t;
    }

    int nb = (tid & 15) << 2;
    int kb = tid >> 4;
    const float* Wp = g_wT + kb * DD + n0 + nb;

    constexpr int NIT = K_CONV / 16;

    auto issue = [&](int it) {
        int slot = it % ST;
        float* as = As[slot];
        float* bs = Bs[slot];
        int kg  = it * 16 + kk;
        int cch = kg / 192;
        int r   = kg - cch * 192;
        int dt  = r >> 6;
        int pix = r & 63;
        int ph  = pix >> 3, pw = pix & 7;
        #pragma unroll
        for (int p = 0; p < 2; p++) {
            int tin = trow[p] + dt - 2;
            bool ok = (tin >= 0);
            const float* src = xb[p] + (ok ? tin : 0) * (CC * HH * WW) + cch * (HH * WW) + ph * WW + pw;
            cp16z(&as[arow[p] * SA + kk], src, ok);
        }
        cp16(&bs[kb * SB + nb], Wp + (size_t)(it * 16) * DD);
        cp_commit();
    };

    issue(0); issue(1);

    int warp_m = (warp >> 1) * 32, warp_n = (warp & 1) * 32;
    float c[2][4][4] = {};
    for (int it = 0; it < NIT; it++) {
        cp_wait<1>();
        __syncthreads();
        mma_tile_conv(As[it % ST], Bs[it % ST], warp_m, warp_n, lane, c);
        if (it + ST - 1 < NIT) issue(it + ST - 1);
        else cp_commit();
    }

    int g = lane >> 2, tg = lane & 3;
    #pragma unroll
    for (int mt = 0; mt < 2; mt++) {
        #pragma unroll
        for (int nt = 0; nt < 4; nt++) {
            int cb = n0 + warp_n + nt * 8 + 2 * tg;
            float b0 = bias[cb], b1 = bias[cb + 1];
            int r0 = m0 + warp_m + mt * 16 + g;
            *(float2*)&g_tok[(size_t)r0 * DD + cb]       = make_float2(c[mt][nt][0] + b0, c[mt][nt][1] + b1);
            *(float2*)&g_tok[(size_t)(r0 + 8) * DD + cb] = make_float2(c[mt][nt][2] + b0, c[mt][nt][3] + b1);
        }
    }
}

// ---------------- token LN + FiLM + spatial mean pool (two-pass) ---------
__global__ __launch_bounds__(512) void pool_film_kernel(
    const float* __restrict__ z, const float* __restrict__ film_w,
    const float* __restrict__ film_b, const float* __restrict__ tokg,
    const float* __restrict__ tokb)
{
    int bt = blockIdx.x;
    int tid = threadIdx.x;
    int warp = tid >> 5, lane = tid & 31;
    __shared__ float mu_s[64], rs_s[64];
    __shared__ float zs[32];
    if (tid < 32) zs[tid] = z[bt * 32 + tid];

    const float* base = g_tok + (size_t)bt * NTOK * DD;
    for (int tt = 0; tt < 4; tt++) {
        int nn = warp * 4 + tt;
        const float* row = base + nn * DD;
        float s1 = 0.f, s2 = 0.f;
        for (int d = lane; d < DD; d += 32) { float v = row[d]; s1 += v; s2 += v * v; }
        #pragma unroll
        for (int off = 16; off; off >>= 1) {
            s1 += __shfl_xor_sync(0xffffffffu, s1, off);
            s2 += __shfl_xor_sync(0xffffffffu, s2, off);
        }
        if (lane == 0) {
            float mu  = s1 * (1.f / DD);
            float var = s2 * (1.f / DD) - mu * mu;
            mu_s[nn] = mu;
            rs_s[nn] = rsqrtf(var + EPSV);
        }
    }
    __syncthreads();
    int d = tid;
    float acc = 0.f;
    #pragma unroll 8
    for (int nn = 0; nn < NTOK; nn++)
        acc += (base[nn * DD + d] - mu_s[nn]) * rs_s[nn];
    float pooled = tokg[d] * (acc * (1.f / NTOK)) + tokb[d];
    float gamma = film_b[d], beta = film_b[DD + d];
    #pragma unroll
    for (int j = 0; j < 32; j++) {
        float zv = zs[j];
        gamma += zv * film_w[j * (2 * DD) + d];
        beta  += zv * film_w[j * (2 * DD) + DD + d];
    }
    g_h[bt * DD + d] = (1.f + 0.5f * gamma) * pooled + 0.5f * beta;
}

// ======================= persistent transformer megakernel =======================

union MegaSmem {
    struct { float As[4][32 * SA]; float Bs[4][16 * SB]; } gm;   // 28672 B
    struct { float As[3][32 * SA]; float Bs[3][16 * SB2]; } mm;  // 46080 B
    struct { float kqv[32][SKV];   float sc[32][33]; } at;       // 28928 B
};

// ---- phase: row LayerNorm (4 rows per block, warp per row) ----
__device__ __forceinline__ void ph_ln(
    const float* in, const float* g, const float* b, float* outp, int bid)
{
    int row  = bid * 4 + (threadIdx.x >> 5);
    int lane = threadIdx.x & 31;
    const float* r = in + row * DD;
    float v[16];
    float s1 = 0.f, s2 = 0.f;
    #pragma unroll
    for (int i = 0; i < 16; i++) {
        v[i] = r[lane + i * 32];
        s1 += v[i]; s2 += v[i] * v[i];
    }
    #pragma unroll
    for (int off = 16; off; off >>= 1) {
        s1 += __shfl_xor_sync(0xffffffffu, s1, off);
        s2 += __shfl_xor_sync(0xffffffffu, s2, off);
    }
    float mu  = s1 * (1.f / DD);
    float var = s2 * (1.f / DD) - mu * mu;
    float rstd = rsqrtf(var + EPSV);
    #pragma unroll
    for (int i = 0; i < 16; i++) {
        int d = lane + i * 32;
        outp[row * DD + d] = f2tf_f((v[i] - mu) * rstd * g[d] + b[d]);
    }
}

// ---- phase: generic GEMM tile (BM=32, BN=64, 4-stage) ----
// EPI 1: out = tf32(gelu(A@W+b)) ; EPI 2: out = res + (*scale_p)*(A@W+b)
template<int EPI>
__device__ __forceinline__ void ph_gemm(
    MegaSmem& u,
    const float* A, const float* W, const float* bias,
    const float* res, const float* scale_p, float* outp,
    int N, int K, int m0, int n0)
{
    constexpr int ST = 4;
    int tid = threadIdx.x;
    int warp = tid >> 5, lane = tid & 31;

    int kk = (tid & 3) << 2;
    int a_r = tid >> 2;
    const float* Ap = A + (size_t)(m0 + a_r) * K + kk;
    int nb = (tid & 15) << 2;
    int kb = tid >> 4;
    const float* Wp = W + (size_t)kb * N + n0 + nb;

    int NIT = K / 16;

    auto issue = [&](int it) {
        int slot = it % ST;
        int k0 = it * 16;
        cp16(&u.gm.As[slot][a_r * SA + kk],       Ap + k0);
        cp16(&u.gm.Bs[slot][kb * SB + nb],        Wp + (size_t)k0 * N);
        cp16(&u.gm.Bs[slot][(kb + 8) * SB + nb],  Wp + (size_t)(k0 + 8) * N);
        cp_commit();
    };

    issue(0); issue(1); issue(2);

    int warp_n = warp * 16;
    int g = lane >> 2, tg = lane & 3;
    float c[2][2][4] = {};
    for (int it = 0; it < NIT; it++) {
        cp_wait<2>();
        __syncthreads();
        const float* As = u.gm.As[it % ST];
        const float* Bs = u.gm.Bs[it % ST];
        const uint32_t* Au = (const uint32_t*)As;
        #pragma unroll
        for (int ks = 0; ks < 16; ks += 8) {
            uint32_t a[2][4], b[2][2];
            #pragma unroll
            for (int mt = 0; mt < 2; mt++) {
                int r0 = mt * 16 + g;
                a[mt][0] = Au[(r0    ) * SA + ks + tg    ];
                a[mt][1] = Au[(r0 + 8) * SA + ks + tg    ];
                a[mt][2] = Au[(r0    ) * SA + ks + tg + 4];
                a[mt][3] = Au[(r0 + 8) * SA + ks + tg + 4];
            }
            #pragma unroll
            for (int nt = 0; nt < 2; nt++) {
                int col = warp_n + nt * 8 + g;
                b[nt][0] = f2tf(Bs[(ks + tg    ) * SB + col]);
                b[nt][1] = f2tf(Bs[(ks + tg + 4) * SB + col]);
            }
            #pragma unroll
            for (int mt = 0; mt < 2; mt++)
                #pragma unroll
                for (int nt = 0; nt < 2; nt++)
                    mma1688(c[mt][nt], a[mt], b[nt]);
        }
        if (it + ST - 1 < NIT) issue(it + ST - 1);
        else cp_commit();
    }

    float s = (EPI == 2) ? *scale_p : 0.f;
    #pragma unroll
    for (int mt = 0; mt < 2; mt++) {
        #pragma unroll
        for (int nt = 0; nt < 2; nt++) {
            int cb = n0 + warp_n + nt * 8 + 2 * tg;
            float b0 = bias[cb], b1 = bias[cb + 1];
            #pragma unroll
            for (int h = 0; h < 2; h++) {
                int r = m0 + mt * 16 + g + h * 8;
                float v0 = c[mt][nt][2 * h]     + b0;
                float v1 = c[mt][nt][2 * h + 1] + b1;
                if (EPI == 1) {
                    v0 = 0.5f * v0 * (1.0f + erff(v0 * 0.70710678118654752f));
                    v1 = 0.5f * v1 * (1.0f + erff(v1 * 0.70710678118654752f));
                    v0 = f2tf_f(v0);
                    v1 = f2tf_f(v1);
                }
                if (EPI == 2) {
                    v0 = res[(size_t)r * N + cb]     + s * v0;
                    v1 = res[(size_t)r * N + cb + 1] + s * v1;
                }
                *(float2*)&outp[(size_t)r * N + cb] = make_float2(v0, v1);
            }
        }
    }
    __syncthreads();   // smem safe for next use by this block
}

// ---- phase: fused kqv GEMM + RoPE + attention (block = head,batch) ----
__device__ __forceinline__ void ph_kqv_attn(
    MegaSmem& u, const float* W, const float* bias, int head, int batch)
{
    int tid = threadIdx.x;
    int warp = tid >> 5, lane = tid & 31;
    int m0 = batch * 32;

    int kk  = (tid & 3) << 2;
    int a_r = tid >> 2;
    const float* Ap = g_xi + (size_t)(m0 + a_r) * DD + kk;
    int brow = tid >> 4;
    int bq   = (tid & 15) << 2;
    const float* Wb = W + head * 64 + bq;

    constexpr int ST = 3;
    constexpr int NIT = DD / 16;

    auto issue = [&](int it) {
        int slot = it % ST;
        int k0 = it * 16;
        cp16(&u.mm.As[slot][a_r * SA + kk], Ap + k0);
        #pragma unroll
        for (int p = 0; p < 3; p++) {
            const float* src = Wb + (size_t)(k0 + brow) * 1536 + p * 512;
            cp16(&u.mm.Bs[slot][brow * SB2 + p * 64 + bq],       src);
            cp16(&u.mm.Bs[slot][(brow + 8) * SB2 + p * 64 + bq], src + (size_t)8 * 1536);
        }
        cp_commit();
    };

    issue(0); issue(1);

    int g  = lane >> 2;
    int tg = lane & 3;
    int warp_n = warp * 48;
    float c[2][6][4] = {};
    for (int it = 0; it < NIT; it++) {
        cp_wait<1>();
        __syncthreads();
        const float* As = u.mm.As[it % ST];
        const float* Bs = u.mm.Bs[it % ST];
        const uint32_t* Au = (const uint32_t*)As;
        #pragma unroll
        for (int ks = 0; ks < 16; ks += 8) {
            uint32_t a[2][4], b[6][2];
            #pragma unroll
            for (int mt = 0; mt < 2; mt++) {
                int r0 = mt * 16 + g;
                a[mt][0] = Au[(r0    ) * SA + ks + tg    ];
                a[mt][1] = Au[(r0 + 8) * SA + ks + tg    ];
                a[mt][2] = Au[(r0    ) * SA + ks + tg + 4];
                a[mt][3] = Au[(r0 + 8) * SA + ks + tg + 4];
            }
            #pragma unroll
            for (int nt = 0; nt < 6; nt++) {
                int col = warp_n + nt * 8 + g;
                b[nt][0] = f2tf(Bs[(ks + tg    ) * SB2 + col]);
                b[nt][1] = f2tf(Bs[(ks + tg + 4) * SB2 + col]);
            }
            #pragma unroll
            for (int mt = 0; mt < 2; mt++)
                #pragma unroll
                for (int nt = 0; nt < 6; nt++)
                    mma1688(c[mt][nt], a[mt], b[nt]);
        }
        if (it + ST - 1 < NIT) issue(it + ST - 1);
        else cp_commit();
    }

    __syncthreads();     // all MMA smem reads done; safe to alias
    #pragma unroll
    for (int mt = 0; mt < 2; mt++) {
        #pragma unroll
        for (int nt = 0; nt < 6; nt++) {
            int col = warp_n + nt * 8 + 2 * tg;
            int p = col >> 6;
            int cbase = p * 512 + head * 64 + (col & 63);
            float b0 = bias[cbase], b1 = bias[cbase + 1];
            int r0 = mt * 16 + g;
            u.at.kqv[r0][col]         = c[mt][nt][0] + b0;
            u.at.kqv[r0][col + 1]     = c[mt][nt][1] + b1;
            u.at.kqv[r0 + 8][col]     = c[mt][nt][2] + b0;
            u.at.kqv[r0 + 8][col + 1] = c[mt][nt][3] + b1;
        }
    }
    __syncthreads();

    // RoPE on k (cols 0..63) and q (cols 64..127)
    #pragma unroll
    for (int i = 0; i < 8; i++) {
        int idx = tid + i * 128;
        int t = idx >> 5, d0 = idx & 31;
        float sn = g_ropes[idx], cs = g_ropec[idx];
        float k0 = u.at.kqv[t][d0],      k1 = u.at.kqv[t][d0 + 32];
        u.at.kqv[t][d0]      = k0 * cs - k1 * sn;
        u.at.kqv[t][d0 + 32] = k1 * cs + k0 * sn;
        float q0 = u.at.kqv[t][64 + d0], q1 = u.at.kqv[t][64 + d0 + 32];
        u.at.kqv[t][64 + d0]      = q0 * cs - q1 * sn;
        u.at.kqv[t][64 + d0 + 32] = q1 * cs + q0 * sn;
    }
    __syncthreads();

    // causal scores
    #pragma unroll
    for (int i = 0; i < 8; i++) {
        int idx = tid + i * 128;
        int tq = idx >> 5, tk = idx & 31;
        float s = -INFINITY;
        if (tk <= tq) {
            s = 0.f;
            #pragma unroll 16
            for (int d2 = 0; d2 < 64; d2++)
                s += u.at.kqv[tq][64 + d2] * u.at.kqv[tk][d2];
            s *= 0.125f;
        }
        u.at.sc[tq][tk] = s;
    }
    __syncthreads();

    // softmax
    #pragma unroll
    for (int i = 0; i < 8; i++) {
        int rw = warp * 8 + i;
        float sv = u.at.sc[rw][lane];
        float mx = sv;
        #pragma unroll
        for (int off = 16; off; off >>= 1) mx = fmaxf(mx, __shfl_xor_sync(0xffffffffu, mx, off));
        float e = expf(sv - mx);
        float sum = e;
        #pragma unroll
        for (int off = 16; off; off >>= 1) sum += __shfl_xor_sync(0xffffffffu, sum, off);
        u.at.sc[rw][lane] = e / sum;
    }
    __syncthreads();

    // out = P @ V
    #pragma unroll
    for (int i = 0; i < 16; i++) {
        int idx = tid + i * 128;
        int tq = idx >> 6, d = idx & 63;
        float a = 0.f;
        for (int tk = 0; tk <= tq; tk++)
            a += u.at.sc[tq][tk] * u.at.kqv[tk][128 + d];
        g_yv[(size_t)(m0 + tq) * DD + head * 64 + d] = f2tf_f(a);
    }
    __syncthreads();
}

// ---- phase: head LN + dot (4 rows per block) ----
__device__ __forceinline__ void ph_head(
    const float* g, const float* bb, const float* w, const float* bias,
    float* outp, int bid)
{
    int row  = bid * 4 + (threadIdx.x >> 5);
    int lane = threadIdx.x & 31;
    const float* r = g_h + row * DD;
    float v[16];
    float s1 = 0.f, s2 = 0.f;
    #pragma unroll
    for (int i = 0; i < 16; i++) {
        v[i] = r[lane + i * 32];
        s1 += v[i]; s2 += v[i] * v[i];
    }
    #pragma unroll
    for (int off = 16; off; off >>= 1) {
        s1 += __shfl_xor_sync(0xffffffffu, s1, off);
        s2 += __shfl_xor_sync(0xffffffffu, s2, off);
    }
    float mu   = s1 * (1.f / DD);
    float var  = s2 * (1.f / DD) - mu * mu;
    float rstd = rsqrtf(var + EPSV);
    float dot = 0.f;
    #pragma unroll
    for (int i = 0; i < 16; i++) {
        int d = lane + i * 32;
        float ln = (v[i] - mu) * rstd * g[d] + bb[d];
        dot += ln * w[d];
    }
    #pragma unroll
    for (int off = 16; off; off >>= 1) dot += __shfl_xor_sync(0xffffffffu, dot, off);
    if (lane == 0) outp[row] = dot + bias[0];
}

__global__ __launch_bounds__(128) void transformer_mega(
    const float* __restrict__ ln1_g, const float* __restrict__ ln1_b,
    const float* __restrict__ kqv_w, const float* __restrict__ kqv_b,
    const float* __restrict__ proj_w, const float* __restrict__ proj_b,
    const float* __restrict__ ln2_g, const float* __restrict__ ln2_b,
    const float* __restrict__ mlp_w1, const float* __restrict__ mlp_b1,
    const float* __restrict__ mlp_w2, const float* __restrict__ mlp_b2,
    const float* __restrict__ rs_attn, const float* __restrict__ rs_mlp,
    const float* __restrict__ head_g, const float* __restrict__ head_b,
    const float* __restrict__ head_w, const float* __restrict__ head_bias,
    float* __restrict__ out)
{
    __shared__ MegaSmem u;
    int bid = blockIdx.x;
    int mb = (bid >> 3) * 32;       // m0 for gemm phases
    int nb = (bid & 7);             // n-tile index 0..7

    for (int l = 0; l < LL; l++) {
        ph_ln(g_h, ln1_g + l * DD, ln1_b + l * DD, g_xi, bid);
        grid_sync();
        ph_kqv_attn(u, kqv_w + (size_t)l * DD * 3 * DD, kqv_b + l * 3 * DD,
                    bid & 7, bid >> 3);
        grid_sync();
        ph_gemm<2>(u, g_yv, proj_w + (size_t)l * DD * DD, proj_b + l * DD,
                   g_h, rs_attn + l, g_h, DD, DD, mb, nb * 64);
        grid_sync();
        ph_ln(g_h, ln2_g + l * DD, ln2_b + l * DD, g_xi, bid);
        grid_sync();
        #pragma unroll 1
        for (int j = 0; j < 4; j++)
            ph_gemm<1>(u, g_xi, mlp_w1 + (size_t)l * DD * 4 * DD, mlp_b1 + l * 4 * DD,
                       nullptr, nullptr, g_mid, 4 * DD, DD, mb, (nb + 8 * j) * 64);
        grid_sync();
        ph_gemm<2>(u, g_mid, mlp_w2 + (size_t)l * 4 * DD * DD, mlp_b2 + l * DD,
                   g_h, rs_mlp + l, g_h, DD, 4 * DD, mb, nb * 64);
        grid_sync();
    }
    ph_head(head_g, head_b, head_w, head_bias, out, bid);
}

// ---------------- launch ----------------
extern "C" void kernel_launch(void* const* d_in, const int* in_sizes, int n_in,
                              void* d_out, int out_size)
{
    const float* x        = (const float*)d_in[0];
    const float* z        = (const float*)d_in[1];
    const float* conv_w   = (const float*)d_in[2];
    const float* conv_b   = (const float*)d_in[3];
    const float* tok_g    = (const float*)d_in[4];
    const float* tok_b    = (const float*)d_in[5];
    const float* film_w   = (const float*)d_in[6];
    const float* film_b   = (const float*)d_in[7];
    const float* ln1_g    = (const float*)d_in[8];
    const float* ln1_b    = (const float*)d_in[9];
    const float* kqv_w    = (const float*)d_in[10];
    const float* kqv_b    = (const float*)d_in[11];
    const float* proj_w   = (const float*)d_in[12];
    const float* proj_b   = (const float*)d_in[13];
    const float* ln2_g    = (const float*)d_in[14];
    const float* ln2_b    = (const float*)d_in[15];
    const float* mlp_w1   = (const float*)d_in[16];
    const float* mlp_b1   = (const float*)d_in[17];
    const float* mlp_w2   = (const float*)d_in[18];
    const float* mlp_b2   = (const float*)d_in[19];
    const float* rs_attn  = (const float*)d_in[20];
    const float* rs_mlp   = (const float*)d_in[21];
    const float* head_g   = (const float*)d_in[22];
    const float* head_b   = (const float*)d_in[23];
    const float* head_w   = (const float*)d_in[24];
    const float* head_bia = (const float*)d_in[25];
    float* out = (float*)d_out;

    transpose_w_kernel<<<(DD * K_CONV + 255) / 256, 256>>>(conv_w);
    rope_kernel<<<1, 1024>>>();
    conv_gemm_tc<<<dim3(8, 256), 256>>>(x, conv_b);
    pool_film_kernel<<<BT, 512>>>(z, film_w, film_b, tok_g, tok_b);

    transformer_mega<<<NBLK, 128>>>(
        ln1_g, ln1_b, kqv_w, kqv_b, proj_w, proj_b, ln2_g, ln2_b,
        mlp_w1, mlp_b1, mlp_w2, mlp_b2, rs_attn, rs_mlp,
        head_g, head_b, head_w, head_bia, out);
}

// round 16
// speedup vs baseline: 1.1956x; 1.1956x over previous
#include <cuda_runtime.h>
#include <math.h>
#include <stdint.h>

// ---------------- problem constants ----------------
#define BB    16
#define TT    32
#define CC    3
#define HH    64
#define WW    64
#define DD    512
#define LL    6
#define BT    512          // B*T
#define NTOK  64           // tokens per frame (8x8)
#define M_CONV 32768       // B*T*NTOK
#define K_CONV 576         // C*KT*P*P
#define EPSV  1e-5f

#define SA    20           // As row stride (floats)
#define SB    72           // Bs row stride (floats)
#define SBC   136          // conv Bs row stride (128 cols + pad)
#define SB2   200          // fused-kernel Bs row stride (192 cols + pad)
#define SKV   193          // fused attn kqv row stride (conflict-free)

// ---------------- scratch (device globals; no allocation) ----------------
__device__ float g_tok[M_CONV * DD];
__device__ float g_wT [K_CONV * DD];     // transposed conv weight, tf32-pre-rounded
__device__ float g_h  [BT * DD];
__device__ float g_xi [BT * DD];         // LN output, tf32-pre-rounded
__device__ float g_yv [BT * DD];         // attn output, tf32-pre-rounded
__device__ float g_mid[BT * 4 * DD];     // gelu output, tf32-pre-rounded
__device__ float g_ropes[TT * 32];
__device__ float g_ropec[TT * 32];

// ---------------- helpers ----------------
__device__ __forceinline__ uint32_t f2tf(float f) {
    uint32_t u;
    asm("cvt.rna.tf32.f32 %0, %1;" : "=r"(u) : "f"(f));
    return u;
}
__device__ __forceinline__ float f2tf_f(float f) {
    return __uint_as_float(f2tf(f));
}

__device__ __forceinline__ void mma1688(float* c, const uint32_t* a, const uint32_t* b) {
    asm volatile(
        "mma.sync.aligned.m16n8k8.row.col.f32.tf32.tf32.f32 "
        "{%0,%1,%2,%3}, {%4,%5,%6,%7}, {%8,%9}, {%0,%1,%2,%3};"
        : "+f"(c[0]), "+f"(c[1]), "+f"(c[2]), "+f"(c[3])
        : "r"(a[0]), "r"(a[1]), "r"(a[2]), "r"(a[3]), "r"(b[0]), "r"(b[1]));
}

__device__ __forceinline__ void cp16(void* smem, const void* gmem) {
    uint32_t s = (uint32_t)__cvta_generic_to_shared(smem);
    asm volatile("cp.async.cg.shared.global [%0], [%1], 16;\n" :: "r"(s), "l"(gmem));
}
__device__ __forceinline__ void cp16z(void* smem, const void* gmem, bool pred) {
    uint32_t s = (uint32_t)__cvta_generic_to_shared(smem);
    int sz = pred ? 16 : 0;
    asm volatile("cp.async.cg.shared.global [%0], [%1], 16, %2;\n" :: "r"(s), "l"(gmem), "r"(sz));
}
__device__ __forceinline__ void cp_commit() {
    asm volatile("cp.async.commit_group;\n");
}
template<int N>
__device__ __forceinline__ void cp_wait() {
    asm volatile("cp.async.wait_group %0;\n" :: "n"(N));
}

// ---------------- weight transpose (+ tf32 pre-round) ----------------
__global__ void transpose_w_kernel(const float* __restrict__ w) {
    int idx = blockIdx.x * 256 + threadIdx.x;
    if (idx < DD * K_CONV) {
        int d = idx / K_CONV, k = idx - d * K_CONV;
        g_wT[k * DD + d] = f2tf_f(w[idx]);
    }
}

// ---------------- RoPE table ----------------
__global__ void rope_kernel() {
    int tid = threadIdx.x;          // 1024 threads
    int t = tid >> 5, d0 = tid & 31;
    float freq = exp2f(-(float)d0 * (13.287712379549449f / 32.f));
    float ang = (float)t * freq;
    float s, c;
    sincosf(ang, &s, &c);
    g_ropes[tid] = s;
    g_ropec[tid] = c;
}

// ---------------- conv as GEMM: BM=128, BN=128, 128 thr, warp tile 64x64 --
// 3-stage cp.async, dynamic smem (56832 B)
__global__ __launch_bounds__(128) void conv_gemm_tc(
    const float* __restrict__ x, const float* __restrict__ bias)
{
    extern __shared__ float sm[];
    constexpr int BM = 128;
    constexpr int ST = 3;
    float* Asb = sm;                         // ST * BM * SA
    float* Bsb = sm + ST * BM * SA;          // ST * 16 * SBC
    int tid = threadIdx.x;
    int warp = tid >> 5, lane = tid & 31;
    int m0 = blockIdx.y * BM, n0 = blockIdx.x * 128;

    int kk = (tid & 3) << 2;
    const float* xb[4];
    int trow[4], arow[4];
    #pragma unroll
    for (int p = 0; p < 4; p++) {
        int row = p * 32 + (tid >> 2);
        arow[p] = row;
        int m = m0 + row;
        int b = m >> 11;
        int t = (m >> 6) & 31;
        int n = m & 63;
        int hn = n >> 3, wn = n & 7;
        xb[p]  = x + b * (TT * CC * HH * WW) + (hn * 8) * WW + wn * 8;
        trow[p] = t;
    }

    int nb = (tid & 31) << 2;
    int kb = tid >> 5;                       // 0..3
    const float* Wp = g_wT + (size_t)kb * DD + n0 + nb;

    constexpr int NIT = K_CONV / 16;         // 36

    auto issue = [&](int it) {
        int slot = it % ST;
        float* as = Asb + slot * (BM * SA);
        float* bs = Bsb + slot * (16 * SBC);
        int kg  = it * 16 + kk;
        int cch = kg / 192;
        int r   = kg - cch * 192;
        int dt  = r >> 6;
        int pix = r & 63;
        int ph  = pix >> 3, pw = pix & 7;
        #pragma unroll
        for (int p = 0; p < 4; p++) {
            int tin = trow[p] + dt - 2;
            bool ok = (tin >= 0);
            const float* src = xb[p] + (ok ? tin : 0) * (CC * HH * WW) + cch * (HH * WW) + ph * WW + pw;
            cp16z(&as[arow[p] * SA + kk], src, ok);
        }
        #pragma unroll
        for (int q = 0; q < 4; q++)
            cp16(&bs[(kb + 4 * q) * SBC + nb],
                 Wp + (size_t)(it * 16 + 4 * q) * DD);
        cp_commit();
    };

    issue(0); issue(1);

    int g  = lane >> 2;
    int tg = lane & 3;
    int warp_m = (warp >> 1) * 64, warp_n = (warp & 1) * 64;
    float c[4][8][4] = {};
    for (int it = 0; it < NIT; it++) {
        cp_wait<1>();
        __syncthreads();
        const float* As = Asb + (it % ST) * (BM * SA);
        const uint32_t* Bu = (const uint32_t*)(Bsb + (it % ST) * (16 * SBC));
        #pragma unroll
        for (int ks = 0; ks < 16; ks += 8) {
            uint32_t a[4][4], b[8][2];
            #pragma unroll
            for (int mt = 0; mt < 4; mt++) {
                int r0 = warp_m + mt * 16 + g;
                a[mt][0] = f2tf(As[(r0    ) * SA + ks + tg    ]);
                a[mt][1] = f2tf(As[(r0 + 8) * SA + ks + tg    ]);
                a[mt][2] = f2tf(As[(r0    ) * SA + ks + tg + 4]);
                a[mt][3] = f2tf(As[(r0 + 8) * SA + ks + tg + 4]);
            }
            #pragma unroll
            for (int nt = 0; nt < 8; nt++) {
                int col = warp_n + nt * 8 + g;
                b[nt][0] = Bu[(ks + tg    ) * SBC + col];
                b[nt][1] = Bu[(ks + tg + 4) * SBC + col];
            }
            #pragma unroll
            for (int mt = 0; mt < 4; mt++)
                #pragma unroll
                for (int nt = 0; nt < 8; nt++)
                    mma1688(c[mt][nt], a[mt], b[nt]);
        }
        if (it + ST - 1 < NIT) issue(it + ST - 1);
        else cp_commit();
        __syncthreads();
    }

    #pragma unroll
    for (int mt = 0; mt < 4; mt++) {
        #pragma unroll
        for (int nt = 0; nt < 8; nt++) {
            int cb = n0 + warp_n + nt * 8 + 2 * tg;
            float b0 = bias[cb], b1 = bias[cb + 1];
            int r0 = m0 + warp_m + mt * 16 + g;
            *(float2*)&g_tok[(size_t)r0 * DD + cb]       = make_float2(c[mt][nt][0] + b0, c[mt][nt][1] + b1);
            *(float2*)&g_tok[(size_t)(r0 + 8) * DD + cb] = make_float2(c[mt][nt][2] + b0, c[mt][nt][3] + b1);
        }
    }
}

// ---- transformer warp tile 32x16: A pre-rounded (plain load), B needs cvt --
__device__ __forceinline__ void mma_tile32(
    const float* As, const float* Bs, int warp_n, int lane, float c[2][2][4])
{
    int g  = lane >> 2;
    int tg = lane & 3;
    const uint32_t* Au = (const uint32_t*)As;
    #pragma unroll
    for (int ks = 0; ks < 16; ks += 8) {
        uint32_t a[2][4], b[2][2];
        #pragma unroll
        for (int mt = 0; mt < 2; mt++) {
            int r0 = mt * 16 + g;
            a[mt][0] = Au[(r0    ) * SA + ks + tg    ];
            a[mt][1] = Au[(r0 + 8) * SA + ks + tg    ];
            a[mt][2] = Au[(r0    ) * SA + ks + tg + 4];
            a[mt][3] = Au[(r0 + 8) * SA + ks + tg + 4];
        }
        #pragma unroll
        for (int nt = 0; nt < 2; nt++) {
            int col = warp_n + nt * 8 + g;
            b[nt][0] = f2tf(Bs[(ks + tg    ) * SB + col]);
            b[nt][1] = f2tf(Bs[(ks + tg + 4) * SB + col]);
        }
        #pragma unroll
        for (int mt = 0; mt < 2; mt++)
            #pragma unroll
            for (int nt = 0; nt < 2; nt++)
                mma1688(c[mt][nt], a[mt], b[nt]);
    }
}

// ---------------- transformer GEMM: BM=32, BN=64, 128 thr, 4-stage -------
// EPI 1: out = tf32(gelu(A@W+b))  (feeds mlp2 A-path)
// EPI 2: out = res + (*scale_p)*(A@W + bias)   (residual, fp32)
template<int EPI>
__global__ __launch_bounds__(128) void gemm_tc(
    const float* __restrict__ A, const float* __restrict__ W,
    const float* __restrict__ bias, const float* __restrict__ res,
    const float* __restrict__ scale_p, float* __restrict__ out,
    int M, int N, int K)
{
    constexpr int BM = 32;
    constexpr int ST = 4;
    __shared__ float As[ST][BM * SA];
    __shared__ float Bs[ST][16 * SB];
    int tid = threadIdx.x;
    int warp = tid >> 5, lane = tid & 31;
    int m0 = blockIdx.y * BM, n0 = blockIdx.x * 64;

    int kk = (tid & 3) << 2;
    int a_r = tid >> 2;
    const float* Ap = A + (size_t)(m0 + a_r) * K + kk;
    int nb = (tid & 15) << 2;
    int kb = tid >> 4;
    const float* Wp = W + (size_t)kb * N + n0 + nb;

    int NIT = K / 16;

    auto issue = [&](int it) {
        int slot = it % ST;
        int k0 = it * 16;
        cp16(&As[slot][a_r * SA + kk],       Ap + k0);
        cp16(&Bs[slot][kb * SB + nb],        Wp + (size_t)k0 * N);
        cp16(&Bs[slot][(kb + 8) * SB + nb],  Wp + (size_t)(k0 + 8) * N);
        cp_commit();
    };

    issue(0); issue(1); issue(2);

    int warp_n = warp * 16;
    float c[2][2][4] = {};
    for (int it = 0; it < NIT; it++) {
        cp_wait<2>();
        __syncthreads();
        mma_tile32(As[it % ST], Bs[it % ST], warp_n, lane, c);
        if (it + ST - 1 < NIT) issue(it + ST - 1);
        else cp_commit();
    }

    float s = (EPI == 2) ? *scale_p : 0.f;
    int g = lane >> 2, tg = lane & 3;
    #pragma unroll
    for (int mt = 0; mt < 2; mt++) {
        #pragma unroll
        for (int nt = 0; nt < 2; nt++) {
            int cb = n0 + warp_n + nt * 8 + 2 * tg;
            float b0 = bias[cb], b1 = bias[cb + 1];
            #pragma unroll
            for (int h = 0; h < 2; h++) {
                int r = m0 + mt * 16 + g + h * 8;
                float v0 = c[mt][nt][2 * h]     + b0;
                float v1 = c[mt][nt][2 * h + 1] + b1;
                if (EPI == 1) {
                    v0 = 0.5f * v0 * (1.0f + erff(v0 * 0.70710678118654752f));
                    v1 = 0.5f * v1 * (1.0f + erff(v1 * 0.70710678118654752f));
                    v0 = f2tf_f(v0);
                    v1 = f2tf_f(v1);
                }
                if (EPI == 2) {
                    v0 = res[(size_t)r * N + cb]     + s * v0;
                    v1 = res[(size_t)r * N + cb + 1] + s * v1;
                }
                *(float2*)&out[(size_t)r * N + cb] = make_float2(v0, v1);
            }
        }
    }
}

// ============ fused kqv GEMM + RoPE + attention ============
union FusedSmem {
    struct { float As[3][32 * SA]; float Bs[3][16 * SB2]; } mm;
    struct { float kqv[32][SKV];   float sc[32][33]; } at;
};

__global__ __launch_bounds__(128) void kqv_attn_kernel(
    const float* __restrict__ W,     // kqv_w layer base [512][1536]
    const float* __restrict__ bias)  // kqv_b layer base [1536]
{
    __shared__ FusedSmem u;
    int tid = threadIdx.x;
    int warp = tid >> 5, lane = tid & 31;
    int head = blockIdx.x, batch = blockIdx.y;
    int m0 = batch * 32;

    int kk  = (tid & 3) << 2;
    int a_r = tid >> 2;
    const float* Ap = g_xi + (size_t)(m0 + a_r) * DD + kk;
    int brow = tid >> 4;
    int bq   = (tid & 15) << 2;
    const float* Wb = W + head * 64 + bq;

    constexpr int ST = 3;
    constexpr int NIT = DD / 16;

    auto issue = [&](int it) {
        int slot = it % ST;
        int k0 = it * 16;
        cp16(&u.mm.As[slot][a_r * SA + kk], Ap + k0);
        #pragma unroll
        for (int p = 0; p < 3; p++) {
            const float* src = Wb + (size_t)(k0 + brow) * 1536 + p * 512;
            cp16(&u.mm.Bs[slot][brow * SB2 + p * 64 + bq],       src);
            cp16(&u.mm.Bs[slot][(brow + 8) * SB2 + p * 64 + bq], src + (size_t)8 * 1536);
        }
        cp_commit();
    };

    issue(0); issue(1);

    int g  = lane >> 2;
    int tg = lane & 3;
    int warp_n = warp * 48;
    float c[2][6][4] = {};
    for (int it = 0; it < NIT; it++) {
        cp_wait<1>();
        __syncthreads();
        const float* As = u.mm.As[it % ST];
        const float* Bs = u.mm.Bs[it % ST];
        const uint32_t* Au = (const uint32_t*)As;
        #pragma unroll
        for (int ks = 0; ks < 16; ks += 8) {
            uint32_t a[2][4], b[6][2];
            #pragma unroll
            for (int mt = 0; mt < 2; mt++) {
                int r0 = mt * 16 + g;
                a[mt][0] = Au[(r0    ) * SA + ks + tg    ];
                a[mt][1] = Au[(r0 + 8) * SA + ks + tg    ];
                a[mt][2] = Au[(r0    ) * SA + ks + tg + 4];
                a[mt][3] = Au[(r0 + 8) * SA + ks + tg + 4];
            }
            #pragma unroll
            for (int nt = 0; nt < 6; nt++) {
                int col = warp_n + nt * 8 + g;
                b[nt][0] = f2tf(Bs[(ks + tg    ) * SB2 + col]);
                b[nt][1] = f2tf(Bs[(ks + tg + 4) * SB2 + col]);
            }
            #pragma unroll
            for (int mt = 0; mt < 2; mt++)
                #pragma unroll
                for (int nt = 0; nt < 6; nt++)
                    mma1688(c[mt][nt], a[mt], b[nt]);
        }
        if (it + ST - 1 < NIT) issue(it + ST - 1);
        else cp_commit();
    }

    __syncthreads();     // all MMA smem reads done; safe to alias
    #pragma unroll
    for (int mt = 0; mt < 2; mt++) {
        #pragma unroll
        for (int nt = 0; nt < 6; nt++) {
            int col = warp_n + nt * 8 + 2 * tg;
            int p = col >> 6;
            int cbase = p * 512 + head * 64 + (col & 63);
            float b0 = bias[cbase], b1 = bias[cbase + 1];
            int r0 = mt * 16 + g;
            u.at.kqv[r0][col]         = c[mt][nt][0] + b0;
            u.at.kqv[r0][col + 1]     = c[mt][nt][1] + b1;
            u.at.kqv[r0 + 8][col]     = c[mt][nt][2] + b0;
            u.at.kqv[r0 + 8][col + 1] = c[mt][nt][3] + b1;
        }
    }
    __syncthreads();

    #pragma unroll
    for (int i = 0; i < 8; i++) {
        int idx = tid + i * 128;
        int t = idx >> 5, d0 = idx & 31;
        float sn = g_ropes[idx], cs = g_ropec[idx];
        float k0 = u.at.kqv[t][d0],      k1 = u.at.kqv[t][d0 + 32];
        u.at.kqv[t][d0]      = k0 * cs - k1 * sn;
        u.at.kqv[t][d0 + 32] = k1 * cs + k0 * sn;
        float q0 = u.at.kqv[t][64 + d0], q1 = u.at.kqv[t][64 + d0 + 32];
        u.at.kqv[t][64 + d0]      = q0 * cs - q1 * sn;
        u.at.kqv[t][64 + d0 + 32] = q1 * cs + q0 * sn;
    }
    __syncthreads();

    #pragma unroll
    for (int i = 0; i < 8; i++) {
        int idx = tid + i * 128;
        int tq = idx >> 5, tk = idx & 31;
        float s = -INFINITY;
        if (tk <= tq) {
            s = 0.f;
            #pragma unroll 16
            for (int d2 = 0; d2 < 64; d2++)
                s += u.at.kqv[tq][64 + d2] * u.at.kqv[tk][d2];
            s *= 0.125f;
        }
        u.at.sc[tq][tk] = s;
    }
    __syncthreads();

    #pragma unroll
    for (int i = 0; i < 8; i++) {
        int rw = warp * 8 + i;
        float sv = u.at.sc[rw][lane];
        float mx = sv;
        #pragma unroll
        for (int off = 16; off; off >>= 1) mx = fmaxf(mx, __shfl_xor_sync(0xffffffffu, mx, off));
        float e = expf(sv - mx);
        float sum = e;
        #pragma unroll
        for (int off = 16; off; off >>= 1) sum += __shfl_xor_sync(0xffffffffu, sum, off);
        u.at.sc[rw][lane] = e / sum;
    }
    __syncthreads();

    #pragma unroll
    for (int i = 0; i < 16; i++) {
        int idx = tid + i * 128;
        int tq = idx >> 6, d = idx & 63;
        float a = 0.f;
        for (int tk = 0; tk <= tq; tk++)
            a += u.at.sc[tq][tk] * u.at.kqv[tk][128 + d];
        g_yv[(size_t)(m0 + tq) * DD + head * 64 + d] = f2tf_f(a);
    }
}

// ---------------- token LN + FiLM + spatial mean pool (two-pass) ---------
__global__ __launch_bounds__(512) void pool_film_kernel(
    const float* __restrict__ z, const float* __restrict__ film_w,
    const float* __restrict__ film_b, const float* __restrict__ tokg,
    const float* __restrict__ tokb)
{
    int bt = blockIdx.x;
    int tid = threadIdx.x;
    int warp = tid >> 5, lane = tid & 31;
    __shared__ float mu_s[64], rs_s[64];
    __shared__ float zs[32];
    if (tid < 32) zs[tid] = z[bt * 32 + tid];

    const float* base = g_tok + (size_t)bt * NTOK * DD;
    for (int tt = 0; tt < 4; tt++) {
        int nn = warp * 4 + tt;
        const float* row = base + nn * DD;
        float s1 = 0.f, s2 = 0.f;
        for (int d = lane; d < DD; d += 32) { float v = row[d]; s1 += v; s2 += v * v; }
        #pragma unroll
        for (int off = 16; off; off >>= 1) {
            s1 += __shfl_xor_sync(0xffffffffu, s1, off);
            s2 += __shfl_xor_sync(0xffffffffu, s2, off);
        }
        if (lane == 0) {
            float mu  = s1 * (1.f / DD);
            float var = s2 * (1.f / DD) - mu * mu;
            mu_s[nn] = mu;
            rs_s[nn] = rsqrtf(var + EPSV);
        }
    }
    __syncthreads();
    int d = tid;
    float acc = 0.f;
    #pragma unroll 8
    for (int nn = 0; nn < NTOK; nn++)
        acc += (base[nn * DD + d] - mu_s[nn]) * rs_s[nn];
    float pooled = tokg[d] * (acc * (1.f / NTOK)) + tokb[d];
    float gamma = film_b[d], beta = film_b[DD + d];
    #pragma unroll
    for (int j = 0; j < 32; j++) {
        float zv = zs[j];
        gamma += zv * film_w[j * (2 * DD) + d];
        beta  += zv * film_w[j * (2 * DD) + DD + d];
    }
    g_h[bt * DD + d] = (1.f + 0.5f * gamma) * pooled + 0.5f * beta;
}

// ---------------- row LayerNorm (pre-rounded output) ---------------------
__global__ __launch_bounds__(128) void ln_kernel(
    const float* __restrict__ in, const float* __restrict__ g,
    const float* __restrict__ b, float* __restrict__ out)
{
    int row  = blockIdx.x * 4 + (threadIdx.x >> 5);
    int lane = threadIdx.x & 31;
    const float* r = in + row * DD;
    float v[16];
    float s1 = 0.f, s2 = 0.f;
    #pragma unroll
    for (int i = 0; i < 16; i++) {
        v[i] = r[lane + i * 32];
        s1 += v[i]; s2 += v[i] * v[i];
    }
    #pragma unroll
    for (int off = 16; off; off >>= 1) {
        s1 += __shfl_xor_sync(0xffffffffu, s1, off);
        s2 += __shfl_xor_sync(0xffffffffu, s2, off);
    }
    float mu  = s1 * (1.f / DD);
    float var = s2 * (1.f / DD) - mu * mu;
    float rstd = rsqrtf(var + EPSV);
    #pragma unroll
    for (int i = 0; i < 16; i++) {
        int d = lane + i * 32;
        out[row * DD + d] = f2tf_f((v[i] - mu) * rstd * g[d] + b[d]);
    }
}

// ---------------- head: LN + dot ----------------------------------------
__global__ __launch_bounds__(256) void head_kernel(
    const float* __restrict__ g, const float* __restrict__ bb,
    const float* __restrict__ w, const float* __restrict__ bias,
    float* __restrict__ out)
{
    int row  = blockIdx.x * 8 + (threadIdx.x >> 5);
    int lane = threadIdx.x & 31;
    const float* r = g_h + row * DD;
    float v[16];
    float s1 = 0.f, s2 = 0.f;
    #pragma unroll
    for (int i = 0; i < 16; i++) {
        v[i] = r[lane + i * 32];
        s1 += v[i]; s2 += v[i] * v[i];
    }
    #pragma unroll
    for (int off = 16; off; off >>= 1) {
        s1 += __shfl_xor_sync(0xffffffffu, s1, off);
        s2 += __shfl_xor_sync(0xffffffffu, s2, off);
    }
    float mu   = s1 * (1.f / DD);
    float var  = s2 * (1.f / DD) - mu * mu;
    float rstd = rsqrtf(var + EPSV);
    float dot = 0.f;
    #pragma unroll
    for (int i = 0; i < 16; i++) {
        int d = lane + i * 32;
        float ln = (v[i] - mu) * rstd * g[d] + bb[d];
        dot += ln * w[d];
    }
    #pragma unroll
    for (int off = 16; off; off >>= 1) dot += __shfl_xor_sync(0xffffffffu, dot, off);
    if (lane == 0) out[row] = dot + bias[0];
}

// ---------------- launch ----------------
extern "C" void kernel_launch(void* const* d_in, const int* in_sizes, int n_in,
                              void* d_out, int out_size)
{
    const float* x        = (const float*)d_in[0];
    const float* z        = (const float*)d_in[1];
    const float* conv_w   = (const float*)d_in[2];
    const float* conv_b   = (const float*)d_in[3];
    const float* tok_g    = (const float*)d_in[4];
    const float* tok_b    = (const float*)d_in[5];
    const float* film_w   = (const float*)d_in[6];
    const float* film_b   = (const float*)d_in[7];
    const float* ln1_g    = (const float*)d_in[8];
    const float* ln1_b    = (const float*)d_in[9];
    const float* kqv_w    = (const float*)d_in[10];
    const float* kqv_b    = (const float*)d_in[11];
    const float* proj_w   = (const float*)d_in[12];
    const float* proj_b   = (const float*)d_in[13];
    const float* ln2_g    = (const float*)d_in[14];
    const float* ln2_b    = (const float*)d_in[15];
    const float* mlp_w1   = (const float*)d_in[16];
    const float* mlp_b1   = (const float*)d_in[17];
    const float* mlp_w2   = (const float*)d_in[18];
    const float* mlp_b2   = (const float*)d_in[19];
    const float* rs_attn  = (const float*)d_in[20];
    const float* rs_mlp   = (const float*)d_in[21];
    const float* head_g   = (const float*)d_in[22];
    const float* head_b   = (const float*)d_in[23];
    const float* head_w   = (const float*)d_in[24];
    const float* head_bia = (const float*)d_in[25];
    float* out = (float*)d_out;

    float *p_xi, *p_yv, *p_mid, *p_h;
    cudaGetSymbolAddress((void**)&p_xi,  g_xi);
    cudaGetSymbolAddress((void**)&p_yv,  g_yv);
    cudaGetSymbolAddress((void**)&p_mid, g_mid);
    cudaGetSymbolAddress((void**)&p_h,   g_h);

    const int conv_smem = 3 * (128 * SA + 16 * SBC) * (int)sizeof(float);  // 56832
    cudaFuncSetAttribute(conv_gemm_tc,
                         cudaFuncAttributeMaxDynamicSharedMemorySize, conv_smem);

    transpose_w_kernel<<<(DD * K_CONV + 255) / 256, 256>>>(conv_w);
    rope_kernel<<<1, 1024>>>();
    conv_gemm_tc<<<dim3(4, 256), 128, conv_smem>>>(x, conv_b);
    pool_film_kernel<<<BT, 512>>>(z, film_w, film_b, tok_g, tok_b);

    for (int i = 0; i < LL; i++) {
        ln_kernel<<<128, 128>>>(p_h, ln1_g + i * DD, ln1_b + i * DD, p_xi);
        kqv_attn_kernel<<<dim3(8, 16), 128>>>(kqv_w + (size_t)i * DD * 3 * DD,
                                              kqv_b + i * 3 * DD);
        gemm_tc<2><<<dim3(8, 16), 128>>>(p_yv, proj_w + (size_t)i * DD * DD,
                                         proj_b + i * DD, p_h, rs_attn + i,
                                         p_h, BT, DD, DD);
        ln_kernel<<<128, 128>>>(p_h, ln2_g + i * DD, ln2_b + i * DD, p_xi);
        gemm_tc<1><<<dim3(32, 16), 128>>>(p_xi, mlp_w1 + (size_t)i * DD * 4 * DD,
                                          mlp_b1 + i * 4 * DD, nullptr, nullptr,
                                          p_mid, BT, 4 * DD, DD);
        gemm_tc<2><<<dim3(8, 16), 128>>>(p_mid, mlp_w2 + (size_t)i * 4 * DD * DD,
                                         mlp_b2 + i * DD, p_h, rs_mlp + i,
                                         p_h, BT, DD, 4 * DD);
    }
    head_kernel<<<64, 256>>>(head_g, head_b, head_w, head_bia, out);
}